// round 13
// baseline (speedup 1.0000x reference)
#include <cuda_runtime.h>
#include <stdint.h>

#define ROWLEN   8192
#define NT       512
#define NPT      16             // ROWLEN / NT
#define NWARP    16
#define KSEL     128
#define NBIN     512            // one bin per thread
#define T0BITS   0x3FF00000u    // 1.875f: count(x>=t0) ~ 249 +/- 16 per N(0,1) row
#define SHIFT1   12             // primary bins: width 2^12 ulps
#define ROWBYTES (ROWLEN * 4)
#define GRID     456            // persistent CTAs (3 per SM x 152 SMs)

// dynamic smem layout (bytes)
#define OFF_ROW0  0
#define OFF_ROW1  32768
#define OFF_HIST  65536
#define OFF_W     (OFF_HIST + NBIN * 4)          // 67584
#define OFF_BC    (OFF_W + 2 * NWARP * 4)        // 67712
#define OFF_RNEXT (OFF_BC + 16)                  // 67728
#define OFF_MBAR  (OFF_RNEXT + 8)                // 67736 (8-aligned)
#define SMEM_SZ   (OFF_MBAR + 16)                // 67752

__device__ unsigned int g_row_ctr;               // dynamic row queue head

__global__ void reset_ctr_kernel() { g_row_ctr = 0u; }

__device__ __forceinline__ uint32_t smem_u32(const void* p) {
    uint32_t a;
    asm("{ .reg .u64 t; cvta.to.shared.u64 t, %1; cvt.u32.u64 %0, t; }"
        : "=r"(a) : "l"(p));
    return a;
}
__device__ __forceinline__ void mbar_init(uint32_t m, uint32_t c) {
    asm volatile("mbarrier.init.shared.b64 [%0], %1;" :: "r"(m), "r"(c) : "memory");
}
__device__ __forceinline__ void mbar_expect_tx(uint32_t m, uint32_t bytes) {
    asm volatile("mbarrier.arrive.expect_tx.shared.b64 _, [%0], %1;"
                 :: "r"(m), "r"(bytes) : "memory");
}
__device__ __forceinline__ void bulk_g2s(uint32_t dst, const void* src,
                                         uint32_t bytes, uint32_t m) {
    asm volatile("cp.async.bulk.shared::cluster.global.mbarrier::complete_tx::bytes "
                 "[%0], [%1], %2, [%3];"
                 :: "r"(dst), "l"(src), "r"(bytes), "r"(m) : "memory");
}
__device__ __forceinline__ void mbar_wait(uint32_t m, uint32_t ph) {
    uint32_t done;
    do {
        asm volatile("{ .reg .pred p; "
                     "mbarrier.try_wait.parity.acquire.cta.shared::cta.b64 p, [%1], %2; "
                     "selp.b32 %0, 1, 0, p; }"
                     : "=r"(done) : "r"(m), "r"(ph) : "memory");
    } while (!done);
}

// Persistent per-row top-K of relu(x). 3 CTAs/SM, DOUBLE-BUFFERED rows: while
// row r is processed from buffer A, row r' streams into buffer B, so the
// per-row mbar_wait is ~zero and DRAM stays saturated. Rows claimed from a
// global atomic queue (no tail). Selection = pre-filtered (t0=1.875) 512-bin
// histogram refinement in positive-float bit space; exact for any input.
// Threshold ties broken by LOWEST COLUMN INDEX (jax.lax.top_k rule) via
// deterministic block scans.
extern __shared__ unsigned char dsm[];
__global__ __launch_bounds__(NT, 3)
void topk_relu_kernel(const float* __restrict__ x, float* __restrict__ out,
                      int rows) {
    const int tid  = threadIdx.x;
    const int wid  = tid >> 5;
    const int lane = tid & 31;

    uint32_t* __restrict__ hist = (uint32_t*)(dsm + OFF_HIST);
    uint32_t* __restrict__ wsm  = (uint32_t*)(dsm + OFF_W);
    uint32_t* __restrict__ bc   = (uint32_t*)(dsm + OFF_BC);
    uint32_t* __restrict__ rnx  = (uint32_t*)(dsm + OFF_RNEXT);
    const uint32_t smbase = smem_u32(dsm);
    const uint32_t mb0 = smbase + OFF_MBAR, mb1 = smbase + OFF_MBAR + 8;

    hist[tid] = 0u;
    if (tid == 0) {
        mbar_init(mb0, 1u);
        mbar_init(mb1, 1u);
        uint32_t a = atomicAdd(&g_row_ctr, 2u);   // claim two rows up front
        rnx[0] = a;
        rnx[1] = a + 1u;
        if (a < (uint32_t)rows)
            { mbar_expect_tx(mb0, ROWBYTES); bulk_g2s(smbase + OFF_ROW0, x + (size_t)a * ROWLEN, ROWBYTES, mb0); }
        if (a + 1u < (uint32_t)rows)
            { mbar_expect_tx(mb1, ROWBYTES); bulk_g2s(smbase + OFF_ROW1, x + (size_t)(a + 1u) * ROWLEN, ROWBYTES, mb1); }
    }
    __syncthreads();

    int rcur = (int)rnx[0];
    int roth = (int)rnx[1];
    uint32_t pcur = 0, poth = 0;
    uint32_t bcur = 0;                           // current buffer id

    // Claims are processed in increasing order, so rcur >= rows implies the
    // other buffer's (later) claim is also >= rows.
    while (rcur < rows) {
        mbar_wait(bcur ? mb1 : mb0, pcur); pcur ^= 1;   // row rcur resident

        const float4* __restrict__ rb4 =
            (const float4*)(dsm + (bcur ? OFF_ROW1 : OFF_ROW0));

        // ==== selection: histogram refinement (bit space of positive floats) ====
        uint32_t lo = T0BITS, rng = 0xFFFFFFFFu;
        int shift = SHIFT1;
        uint32_t above = 0u;
        bool clamped = true, first = true;
        uint32_t Tb = 1u, quota = 0u;
        int tie_path = 0;

        for (;;) {
            // ---- histogram (reads row from smem) ----
            if (first) {
#pragma unroll
                for (int i = 0; i < 4; i++) {
                    float4 f = rb4[tid + i * NT];
                    uint32_t b0 = (__float_as_uint(f.x) - T0BITS) >> SHIFT1;
                    uint32_t b1 = (__float_as_uint(f.y) - T0BITS) >> SHIFT1;
                    uint32_t b2 = (__float_as_uint(f.z) - T0BITS) >> SHIFT1;
                    uint32_t b3 = (__float_as_uint(f.w) - T0BITS) >> SHIFT1;
                    if (f.x >= 1.875f) atomicAdd(&hist[b0 < NBIN - 1u ? b0 : NBIN - 1u], 1u);
                    if (f.y >= 1.875f) atomicAdd(&hist[b1 < NBIN - 1u ? b1 : NBIN - 1u], 1u);
                    if (f.z >= 1.875f) atomicAdd(&hist[b2 < NBIN - 1u ? b2 : NBIN - 1u], 1u);
                    if (f.w >= 1.875f) atomicAdd(&hist[b3 < NBIN - 1u ? b3 : NBIN - 1u], 1u);
                }
            } else {
                const float lof = __uint_as_float(lo);
#pragma unroll
                for (int i = 0; i < 4; i++) {
                    float4 f = rb4[tid + i * NT];
                    const float fv[4] = {f.x, f.y, f.z, f.w};
#pragma unroll
                    for (int e = 0; e < 4; e++) {
                        if (fv[e] >= lof) {
                            uint32_t d = __float_as_uint(fv[e]) - lo;
                            if (d < rng) {
                                uint32_t b = d >> shift;
                                if (b > NBIN - 1u) b = NBIN - 1u;
                                atomicAdd(&hist[b], 1u);
                            }
                        }
                    }
                }
            }
            __syncthreads();                   // B1: histogram complete

            // ---- two-level suffix logic (bins descend as tid ascends) ----
            const int rb = NBIN - 1 - tid;
            const uint32_t h = hist[rb];
            hist[rb] = 0u;                     // re-zero for next use
            if (tid == 0) bc[3] = 0u;
            const uint32_t wtot = __reduce_add_sync(0xFFFFFFFFu, h);
            if (lane == 0) wsm[wid] = wtot;
            __syncthreads();                   // B2: warp totals ready

            uint32_t t = (lane < NWARP) ? wsm[lane] : 0u;
            uint32_t sc = t;
#pragma unroll
            for (int o = 1; o < 16; o <<= 1) {
                uint32_t u = __shfl_up_sync(0xFFFFFFFFu, sc, o);
                if (lane >= o) sc += u;
            }
            const uint32_t basew = (wid == 0) ? 0u
                                   : __shfl_sync(0xFFFFFFFFu, sc, wid - 1);
            const uint32_t total = __shfl_sync(0xFFFFFFFFu, sc, NWARP - 1);

            const uint32_t pre = above + basew;
            if (pre < KSEL && pre + wtot >= KSEL) {   // crossing warp only
                uint32_t incl = h;
#pragma unroll
                for (int o = 1; o < 32; o <<= 1) {
                    uint32_t u = __shfl_up_sync(0xFFFFFFFFu, incl, o);
                    if (lane >= o) incl += u;
                }
                const uint32_t suf = pre + incl;
                if (suf >= KSEL && suf - h < KSEL) {
                    bc[0] = (uint32_t)rb;
                    bc[1] = suf - h;
                    bc[2] = h;
                    bc[3] = 1u;
                }
            }
            __syncthreads();                   // B3: crossing published

            if (bc[3] == 0u) {
                if (first) {                   // count(>= t0) < K: search (0, t0)
                    above = total;
                    lo = 1u; rng = T0BITS - 1u; shift = 21;
                    clamped = false; first = false;
                    continue;
                }
                Tb = 1u; tie_path = 0; break;  // <K positives: output = relu(x)
            }
            first = false;
            const uint32_t bstar = bc[0];
            above = bc[1];
            const uint32_t hb = bc[2];
            const uint32_t rk = KSEL - above;
            lo += bstar << shift;
            if (rk == hb) { Tb = lo; tie_path = 0; break; }
            if (shift == 0) { Tb = lo; quota = rk; tie_path = 1; break; }
            if (clamped && bstar == NBIN - 1u) {
                rng = 0xFFFFFFFFu; shift = 23; clamped = false;
            } else {
                rng = 1u << shift;
                shift = (shift > 9) ? (shift - 9) : 0;
                clamped = false;
            }
        }

        // ==== output (re-read row from smem, single HBM write) ====
        float4* __restrict__ ov = reinterpret_cast<float4*>(out + (size_t)rcur * ROWLEN);
        const float T = __uint_as_float(Tb);

        if (!tie_path) {
#pragma unroll
            for (int i = 0; i < 4; i++) {
                float4 f = rb4[tid + i * NT];
                float4 o;
                o.x = (f.x >= T) ? f.x : 0.0f;
                o.y = (f.y >= T) ? f.y : 0.0f;
                o.z = (f.z >= T) ? f.z : 0.0f;
                o.w = (f.w >= T) ? f.w : 0.0f;
                ov[tid + i * NT] = o;
            }
        } else {
            // duplicates straddle rank K: keep `quota` lowest-index ties.
            // column(i,tid,e) = 4*(i*NT+tid)+e  => order (i, tid, e).
            uint32_t tc[4];
            float4 fr[4];
#pragma unroll
            for (int i = 0; i < 4; i++) {
                float4 f = rb4[tid + i * NT];
                fr[i] = f;
                tc[i] = (f.x == T) + (f.y == T) + (f.z == T) + (f.w == T);
            }
            uint32_t packA = tc[0] | (tc[1] << 16);
            uint32_t packB = tc[2] | (tc[3] << 16);

            uint32_t inclA = packA, inclB = packB;
#pragma unroll
            for (int o = 1; o < 32; o <<= 1) {
                uint32_t uA = __shfl_up_sync(0xFFFFFFFFu, inclA, o);
                uint32_t uB = __shfl_up_sync(0xFFFFFFFFu, inclB, o);
                if (lane >= o) { inclA += uA; inclB += uB; }
            }
            if (lane == 31) { wsm[wid] = inclA; wsm[NWARP + wid] = inclB; }
            __syncthreads();
            uint32_t tA = (lane < NWARP) ? wsm[lane] : 0u;
            uint32_t tB = (lane < NWARP) ? wsm[NWARP + lane] : 0u;
            uint32_t sA = tA, sB = tB;
#pragma unroll
            for (int o = 1; o < 16; o <<= 1) {
                uint32_t uA = __shfl_up_sync(0xFFFFFFFFu, sA, o);
                uint32_t uB = __shfl_up_sync(0xFFFFFFFFu, sB, o);
                if (lane >= o) { sA += uA; sB += uB; }
            }
            uint32_t baseA = (wid == 0) ? 0u : __shfl_sync(0xFFFFFFFFu, sA, wid - 1);
            uint32_t baseB = (wid == 0) ? 0u : __shfl_sync(0xFFFFFFFFu, sB, wid - 1);
            uint32_t totA  = __shfl_sync(0xFFFFFFFFu, sA, NWARP - 1);
            uint32_t totB  = __shfl_sync(0xFFFFFFFFu, sB, NWARP - 1);

            const uint32_t exclA = baseA + inclA - packA;
            const uint32_t exclB = baseB + inclB - packB;
            const uint32_t tot0 = totA & 0xFFFFu;
            const uint32_t tot1 = totA >> 16;
            const uint32_t tot2 = totB & 0xFFFFu;

            uint32_t rank[4];
            rank[0] = exclA & 0xFFFFu;
            rank[1] = tot0 + (exclA >> 16);
            rank[2] = tot0 + tot1 + (exclB & 0xFFFFu);
            rank[3] = tot0 + tot1 + tot2 + (exclB >> 16);

#pragma unroll
            for (int i = 0; i < 4; i++) {
                float4 f = fr[i];
                float4 o; uint32_t rk2 = rank[i];
                o.x = (f.x > T) ? f.x : ((f.x == T && rk2++ < quota) ? f.x : 0.0f);
                o.y = (f.y > T) ? f.y : ((f.y == T && rk2++ < quota) ? f.y : 0.0f);
                o.z = (f.z > T) ? f.z : ((f.z == T && rk2++ < quota) ? f.z : 0.0f);
                o.w = (f.w > T) ? f.w : ((f.w == T && rk2++ < quota) ? f.w : 0.0f);
                ov[tid + i * NT] = o;
            }
        }

        if (tid == 0) rnx[0] = atomicAdd(&g_row_ctr, 1u);  // claim next row
        __syncthreads();                       // B4: row reads done + claim visible
        int rn = (int)rnx[0];
        if (tid == 0 && rn < rows) {           // refill the just-freed buffer
            mbar_expect_tx(bcur ? mb1 : mb0, ROWBYTES);
            bulk_g2s(smbase + (bcur ? OFF_ROW1 : OFF_ROW0),
                     x + (size_t)rn * ROWLEN, ROWBYTES, bcur ? mb1 : mb0);
        }
        // rotate: other buffer becomes current; refilled one becomes other
        rcur = roth; roth = rn;
        uint32_t tp = pcur; pcur = poth; poth = tp;
        bcur ^= 1u;
    }
}

extern "C" void kernel_launch(void* const* d_in, const int* in_sizes, int n_in,
                              void* d_out, int out_size) {
    const float* x = (const float*)d_in[0];
    float* out = (float*)d_out;
    int rows = in_sizes[0] / ROWLEN;
    int grid = (rows < GRID) ? rows : GRID;
    cudaFuncSetAttribute(topk_relu_kernel,
                         cudaFuncAttributeMaxDynamicSharedMemorySize, SMEM_SZ);
    reset_ctr_kernel<<<1, 1>>>();
    topk_relu_kernel<<<grid, NT, SMEM_SZ>>>(x, out, rows);
}

// round 14
// speedup vs baseline: 1.0063x; 1.0063x over previous
#include <cuda_runtime.h>
#include <stdint.h>

#define ROWLEN   8192
#define NT       512
#define NPT      16             // ROWLEN / NT
#define NWARP    16
#define KSEL     128
#define NBIN     512            // one bin per thread
#define T0BITS   0x3FF00000u    // 1.875f: count(x>=t0) ~ 249 +/- 16 per N(0,1) row
#define SHIFT1   12             // primary bins: width 2^12 ulps
#define ROWBYTES (ROWLEN * 4)
#define GRID     456            // persistent CTAs (3 per SM x 152 SMs)

// dynamic smem layout (bytes)
#define OFF_ROW0  0
#define OFF_ROW1  32768
#define OFF_HIST  65536
#define OFF_W     (OFF_HIST + NBIN * 4)          // 67584
#define OFF_BC    (OFF_W + 2 * NWARP * 4)        // 67712
#define OFF_RNEXT (OFF_BC + 16)                  // 67728
#define OFF_MBAR  (OFF_RNEXT + 8)                // 67736 (8-aligned)
#define SMEM_SZ   (OFF_MBAR + 16)                // 67752

// Self-resetting work queue: both counters are 0 at entry to EVERY launch
// (static init for the first; the last CTA of each launch resets them before
// exit). No separate reset kernel -> single graph node.
__device__ unsigned int g_row_ctr = 0u;
__device__ unsigned int g_done    = 0u;

__device__ __forceinline__ uint32_t smem_u32(const void* p) {
    uint32_t a;
    asm("{ .reg .u64 t; cvta.to.shared.u64 t, %1; cvt.u32.u64 %0, t; }"
        : "=r"(a) : "l"(p));
    return a;
}
__device__ __forceinline__ void mbar_init(uint32_t m, uint32_t c) {
    asm volatile("mbarrier.init.shared.b64 [%0], %1;" :: "r"(m), "r"(c) : "memory");
}
__device__ __forceinline__ void mbar_expect_tx(uint32_t m, uint32_t bytes) {
    asm volatile("mbarrier.arrive.expect_tx.shared.b64 _, [%0], %1;"
                 :: "r"(m), "r"(bytes) : "memory");
}
__device__ __forceinline__ void bulk_g2s(uint32_t dst, const void* src,
                                         uint32_t bytes, uint32_t m) {
    asm volatile("cp.async.bulk.shared::cluster.global.mbarrier::complete_tx::bytes "
                 "[%0], [%1], %2, [%3];"
                 :: "r"(dst), "l"(src), "r"(bytes), "r"(m) : "memory");
}
__device__ __forceinline__ void mbar_wait(uint32_t m, uint32_t ph) {
    uint32_t done;
    do {
        asm volatile("{ .reg .pred p; "
                     "mbarrier.try_wait.parity.acquire.cta.shared::cta.b64 p, [%1], %2; "
                     "selp.b32 %0, 1, 0, p; }"
                     : "=r"(done) : "r"(m), "r"(ph) : "memory");
    } while (!done);
}

// Persistent per-row top-K of relu(x). 3 CTAs/SM, double-buffered rows (TMA
// for row r' streams while row r is processed -> near-zero per-row waits).
// Rows claimed from a self-resetting global atomic queue (no tail, no reset
// kernel). Output uses streaming stores (.cs) to keep dead write data from
// evicting the input prefetch stream in L2. Selection = pre-filtered
// (t0=1.875) 512-bin histogram refinement in positive-float bit space; exact
// for any input. Threshold ties broken by LOWEST COLUMN INDEX (jax.lax.top_k
// rule) via deterministic block scans.
extern __shared__ unsigned char dsm[];
__global__ __launch_bounds__(NT, 3)
void topk_relu_kernel(const float* __restrict__ x, float* __restrict__ out,
                      int rows) {
    const int tid  = threadIdx.x;
    const int wid  = tid >> 5;
    const int lane = tid & 31;

    uint32_t* __restrict__ hist = (uint32_t*)(dsm + OFF_HIST);
    uint32_t* __restrict__ wsm  = (uint32_t*)(dsm + OFF_W);
    uint32_t* __restrict__ bc   = (uint32_t*)(dsm + OFF_BC);
    uint32_t* __restrict__ rnx  = (uint32_t*)(dsm + OFF_RNEXT);
    const uint32_t smbase = smem_u32(dsm);
    const uint32_t mb0 = smbase + OFF_MBAR, mb1 = smbase + OFF_MBAR + 8;

    hist[tid] = 0u;
    if (tid == 0) {
        mbar_init(mb0, 1u);
        mbar_init(mb1, 1u);
        uint32_t a = atomicAdd(&g_row_ctr, 2u);   // claim two rows up front
        rnx[0] = a;
        rnx[1] = a + 1u;
        if (a < (uint32_t)rows)
            { mbar_expect_tx(mb0, ROWBYTES); bulk_g2s(smbase + OFF_ROW0, x + (size_t)a * ROWLEN, ROWBYTES, mb0); }
        if (a + 1u < (uint32_t)rows)
            { mbar_expect_tx(mb1, ROWBYTES); bulk_g2s(smbase + OFF_ROW1, x + (size_t)(a + 1u) * ROWLEN, ROWBYTES, mb1); }
    }
    __syncthreads();

    int rcur = (int)rnx[0];
    int roth = (int)rnx[1];
    uint32_t pcur = 0, poth = 0;
    uint32_t bcur = 0;                           // current buffer id

    // Claims are processed in increasing order, so rcur >= rows implies the
    // other buffer's (later) claim is also >= rows.
    while (rcur < rows) {
        mbar_wait(bcur ? mb1 : mb0, pcur); pcur ^= 1;   // row rcur resident

        const float4* __restrict__ rb4 =
            (const float4*)(dsm + (bcur ? OFF_ROW1 : OFF_ROW0));

        // ==== selection: histogram refinement (bit space of positive floats) ====
        uint32_t lo = T0BITS, rng = 0xFFFFFFFFu;
        int shift = SHIFT1;
        uint32_t above = 0u;
        bool clamped = true, first = true;
        uint32_t Tb = 1u, quota = 0u;
        int tie_path = 0;

        for (;;) {
            // ---- histogram (reads row from smem) ----
            if (first) {
#pragma unroll
                for (int i = 0; i < 4; i++) {
                    float4 f = rb4[tid + i * NT];
                    uint32_t b0 = (__float_as_uint(f.x) - T0BITS) >> SHIFT1;
                    uint32_t b1 = (__float_as_uint(f.y) - T0BITS) >> SHIFT1;
                    uint32_t b2 = (__float_as_uint(f.z) - T0BITS) >> SHIFT1;
                    uint32_t b3 = (__float_as_uint(f.w) - T0BITS) >> SHIFT1;
                    if (f.x >= 1.875f) atomicAdd(&hist[b0 < NBIN - 1u ? b0 : NBIN - 1u], 1u);
                    if (f.y >= 1.875f) atomicAdd(&hist[b1 < NBIN - 1u ? b1 : NBIN - 1u], 1u);
                    if (f.z >= 1.875f) atomicAdd(&hist[b2 < NBIN - 1u ? b2 : NBIN - 1u], 1u);
                    if (f.w >= 1.875f) atomicAdd(&hist[b3 < NBIN - 1u ? b3 : NBIN - 1u], 1u);
                }
            } else {
                const float lof = __uint_as_float(lo);
#pragma unroll
                for (int i = 0; i < 4; i++) {
                    float4 f = rb4[tid + i * NT];
                    const float fv[4] = {f.x, f.y, f.z, f.w};
#pragma unroll
                    for (int e = 0; e < 4; e++) {
                        if (fv[e] >= lof) {
                            uint32_t d = __float_as_uint(fv[e]) - lo;
                            if (d < rng) {
                                uint32_t b = d >> shift;
                                if (b > NBIN - 1u) b = NBIN - 1u;
                                atomicAdd(&hist[b], 1u);
                            }
                        }
                    }
                }
            }
            __syncthreads();                   // B1: histogram complete

            // ---- two-level suffix logic (bins descend as tid ascends) ----
            const int rb = NBIN - 1 - tid;
            const uint32_t h = hist[rb];
            hist[rb] = 0u;                     // re-zero for next use
            if (tid == 0) bc[3] = 0u;
            const uint32_t wtot = __reduce_add_sync(0xFFFFFFFFu, h);
            if (lane == 0) wsm[wid] = wtot;
            __syncthreads();                   // B2: warp totals ready

            uint32_t t = (lane < NWARP) ? wsm[lane] : 0u;
            uint32_t sc = t;
#pragma unroll
            for (int o = 1; o < 16; o <<= 1) {
                uint32_t u = __shfl_up_sync(0xFFFFFFFFu, sc, o);
                if (lane >= o) sc += u;
            }
            const uint32_t basew = (wid == 0) ? 0u
                                   : __shfl_sync(0xFFFFFFFFu, sc, wid - 1);
            const uint32_t total = __shfl_sync(0xFFFFFFFFu, sc, NWARP - 1);

            const uint32_t pre = above + basew;
            if (pre < KSEL && pre + wtot >= KSEL) {   // crossing warp only
                uint32_t incl = h;
#pragma unroll
                for (int o = 1; o < 32; o <<= 1) {
                    uint32_t u = __shfl_up_sync(0xFFFFFFFFu, incl, o);
                    if (lane >= o) incl += u;
                }
                const uint32_t suf = pre + incl;
                if (suf >= KSEL && suf - h < KSEL) {
                    bc[0] = (uint32_t)rb;
                    bc[1] = suf - h;
                    bc[2] = h;
                    bc[3] = 1u;
                }
            }
            __syncthreads();                   // B3: crossing published

            if (bc[3] == 0u) {
                if (first) {                   // count(>= t0) < K: search (0, t0)
                    above = total;
                    lo = 1u; rng = T0BITS - 1u; shift = 21;
                    clamped = false; first = false;
                    continue;
                }
                Tb = 1u; tie_path = 0; break;  // <K positives: output = relu(x)
            }
            first = false;
            const uint32_t bstar = bc[0];
            above = bc[1];
            const uint32_t hb = bc[2];
            const uint32_t rk = KSEL - above;
            lo += bstar << shift;
            if (rk == hb) { Tb = lo; tie_path = 0; break; }
            if (shift == 0) { Tb = lo; quota = rk; tie_path = 1; break; }
            if (clamped && bstar == NBIN - 1u) {
                rng = 0xFFFFFFFFu; shift = 23; clamped = false;
            } else {
                rng = 1u << shift;
                shift = (shift > 9) ? (shift - 9) : 0;
                clamped = false;
            }
        }

        // ==== output (re-read row from smem; streaming stores) ====
        float4* __restrict__ ov = reinterpret_cast<float4*>(out + (size_t)rcur * ROWLEN);
        const float T = __uint_as_float(Tb);

        if (!tie_path) {
#pragma unroll
            for (int i = 0; i < 4; i++) {
                float4 f = rb4[tid + i * NT];
                float4 o;
                o.x = (f.x >= T) ? f.x : 0.0f;
                o.y = (f.y >= T) ? f.y : 0.0f;
                o.z = (f.z >= T) ? f.z : 0.0f;
                o.w = (f.w >= T) ? f.w : 0.0f;
                __stcs(&ov[tid + i * NT], o);
            }
        } else {
            // duplicates straddle rank K: keep `quota` lowest-index ties.
            // column(i,tid,e) = 4*(i*NT+tid)+e  => order (i, tid, e).
            uint32_t tc[4];
            float4 fr[4];
#pragma unroll
            for (int i = 0; i < 4; i++) {
                float4 f = rb4[tid + i * NT];
                fr[i] = f;
                tc[i] = (f.x == T) + (f.y == T) + (f.z == T) + (f.w == T);
            }
            uint32_t packA = tc[0] | (tc[1] << 16);
            uint32_t packB = tc[2] | (tc[3] << 16);

            uint32_t inclA = packA, inclB = packB;
#pragma unroll
            for (int o = 1; o < 32; o <<= 1) {
                uint32_t uA = __shfl_up_sync(0xFFFFFFFFu, inclA, o);
                uint32_t uB = __shfl_up_sync(0xFFFFFFFFu, inclB, o);
                if (lane >= o) { inclA += uA; inclB += uB; }
            }
            if (lane == 31) { wsm[wid] = inclA; wsm[NWARP + wid] = inclB; }
            __syncthreads();
            uint32_t tA = (lane < NWARP) ? wsm[lane] : 0u;
            uint32_t tB = (lane < NWARP) ? wsm[NWARP + lane] : 0u;
            uint32_t sA = tA, sB = tB;
#pragma unroll
            for (int o = 1; o < 16; o <<= 1) {
                uint32_t uA = __shfl_up_sync(0xFFFFFFFFu, sA, o);
                uint32_t uB = __shfl_up_sync(0xFFFFFFFFu, sB, o);
                if (lane >= o) { sA += uA; sB += uB; }
            }
            uint32_t baseA = (wid == 0) ? 0u : __shfl_sync(0xFFFFFFFFu, sA, wid - 1);
            uint32_t baseB = (wid == 0) ? 0u : __shfl_sync(0xFFFFFFFFu, sB, wid - 1);
            uint32_t totA  = __shfl_sync(0xFFFFFFFFu, sA, NWARP - 1);
            uint32_t totB  = __shfl_sync(0xFFFFFFFFu, sB, NWARP - 1);

            const uint32_t exclA = baseA + inclA - packA;
            const uint32_t exclB = baseB + inclB - packB;
            const uint32_t tot0 = totA & 0xFFFFu;
            const uint32_t tot1 = totA >> 16;
            const uint32_t tot2 = totB & 0xFFFFu;

            uint32_t rank[4];
            rank[0] = exclA & 0xFFFFu;
            rank[1] = tot0 + (exclA >> 16);
            rank[2] = tot0 + tot1 + (exclB & 0xFFFFu);
            rank[3] = tot0 + tot1 + tot2 + (exclB >> 16);

#pragma unroll
            for (int i = 0; i < 4; i++) {
                float4 f = fr[i];
                float4 o; uint32_t rk2 = rank[i];
                o.x = (f.x > T) ? f.x : ((f.x == T && rk2++ < quota) ? f.x : 0.0f);
                o.y = (f.y > T) ? f.y : ((f.y == T && rk2++ < quota) ? f.y : 0.0f);
                o.z = (f.z > T) ? f.z : ((f.z == T && rk2++ < quota) ? f.z : 0.0f);
                o.w = (f.w > T) ? f.w : ((f.w == T && rk2++ < quota) ? f.w : 0.0f);
                __stcs(&ov[tid + i * NT], o);
            }
        }

        if (tid == 0) rnx[0] = atomicAdd(&g_row_ctr, 1u);  // claim next row
        __syncthreads();                       // B4: row reads done + claim visible
        int rn = (int)rnx[0];
        if (tid == 0 && rn < rows) {           // refill the just-freed buffer
            mbar_expect_tx(bcur ? mb1 : mb0, ROWBYTES);
            bulk_g2s(smbase + (bcur ? OFF_ROW1 : OFF_ROW0),
                     x + (size_t)rn * ROWLEN, ROWBYTES, bcur ? mb1 : mb0);
        }
        // rotate: other buffer becomes current; refilled one becomes other
        rcur = roth; roth = rn;
        uint32_t tp = pcur; pcur = poth; poth = tp;
        bcur ^= 1u;
    }

    // ---- self-reset the queue: last CTA out restores counters to 0 ----
    if (tid == 0) {
        __threadfence();
        unsigned d = atomicAdd(&g_done, 1u);
        if (d == gridDim.x - 1u) {
            g_row_ctr = 0u;
            g_done    = 0u;
            __threadfence();
        }
    }
}

extern "C" void kernel_launch(void* const* d_in, const int* in_sizes, int n_in,
                              void* d_out, int out_size) {
    const float* x = (const float*)d_in[0];
    float* out = (float*)d_out;
    int rows = in_sizes[0] / ROWLEN;
    int grid = (rows < GRID) ? rows : GRID;
    cudaFuncSetAttribute(topk_relu_kernel,
                         cudaFuncAttributeMaxDynamicSharedMemorySize, SMEM_SZ);
    topk_relu_kernel<<<grid, NT, SMEM_SZ>>>(x, out, rows);
}